// round 9
// baseline (speedup 1.0000x reference)
#include <cuda_runtime.h>
#include <cuda_bf16.h>
#include <stdint.h>

// ---------------- problem constants ----------------
#define NBAGS 512
#define MSENT 8
#define TLEN  64
#define IND   360
#define HID   230
#define OUTD  53
#define NDOCS 32
#define NENT  8

#define BATCH (NBAGS*MSENT)   // 4096
#define G3    (3*HID)         // 690
#define HH2   (2*HID)         // 460
#define MTOK  (BATCH*TLEN)    // 262144
#define NPART 4

// padded dims
#define KP_IN   384
#define KP_HID  256
#define KP_HH2  512
#define NP_G3   768           // = 4 j-tiles * 192 packed cols
#define NP_HH2  512
#define NP_OUT  128

// ---------------- fp32 scratch ----------------
__device__ __align__(256) float g_xg_f[(size_t)MTOK*NP_G3];   // permuted (jt,gate,jl)
__device__ __align__(256) float g_xg_r[(size_t)MTOK*NP_G3];
__device__ __align__(256) float g_out [(size_t)TLEN*BATCH*HH2];
__device__ __align__(256) float g_partial [(size_t)MTOK*NPART];
__device__ __align__(256) float g_scores  [(size_t)BATCH*TLEN];
__device__ __align__(256) float g_wordvec [(size_t)BATCH*HH2];
__device__ __align__(256) float g_partial2[(size_t)BATCH*NPART];
__device__ __align__(256) float g_scores2 [BATCH];
__device__ __align__(256) float g_bagout  [(size_t)NBAGS*OUTD];
__device__ __align__(256) float g_bhhp [2*4*192];             // packed b_hh

// ---------------- bf16 hi/lo operand scratch ----------------
__device__ __align__(256) __nv_bfloat16 g_bag_hi[(size_t)MTOK*KP_IN];
__device__ __align__(256) __nv_bfloat16 g_bag_lo[(size_t)MTOK*KP_IN];
__device__ __align__(256) __nv_bfloat16 g_outb_hi[(size_t)MTOK*KP_HH2];
__device__ __align__(256) __nv_bfloat16 g_outb_lo[(size_t)MTOK*KP_HH2];
__device__ __align__(256) __nv_bfloat16 g_h_hi[(size_t)2*BATCH*KP_HID];
__device__ __align__(256) __nv_bfloat16 g_h_lo[(size_t)2*BATCH*KP_HID];
__device__ __align__(256) __nv_bfloat16 g_wv_hi[(size_t)BATCH*KP_HH2];
__device__ __align__(256) __nv_bfloat16 g_wv_lo[(size_t)BATCH*KP_HH2];
__device__ __align__(256) __nv_bfloat16 g_sv_hi[(size_t)NBAGS*KP_HH2];
__device__ __align__(256) __nv_bfloat16 g_sv_lo[(size_t)NBAGS*KP_HH2];
__device__ __align__(256) __nv_bfloat16 g_Wihf_hi[(size_t)NP_G3*KP_IN];
__device__ __align__(256) __nv_bfloat16 g_Wihf_lo[(size_t)NP_G3*KP_IN];
__device__ __align__(256) __nv_bfloat16 g_Wihr_hi[(size_t)NP_G3*KP_IN];
__device__ __align__(256) __nv_bfloat16 g_Wihr_lo[(size_t)NP_G3*KP_IN];
__device__ __align__(256) __nv_bfloat16 g_Whhp_hi[(size_t)2*4*192*KP_HID];  // packed (dir,jt,gate*64+jl,k)
__device__ __align__(256) __nv_bfloat16 g_Whhp_lo[(size_t)2*4*192*KP_HID];
__device__ __align__(256) __nv_bfloat16 g_Ww_hi[(size_t)NP_HH2*KP_HH2];
__device__ __align__(256) __nv_bfloat16 g_Ww_lo[(size_t)NP_HH2*KP_HH2];
__device__ __align__(256) __nv_bfloat16 g_Ws_hi[(size_t)NP_HH2*KP_HH2];
__device__ __align__(256) __nv_bfloat16 g_Ws_lo[(size_t)NP_HH2*KP_HH2];
__device__ __align__(256) __nv_bfloat16 g_fc_hi[(size_t)NP_OUT*KP_HH2];
__device__ __align__(256) __nv_bfloat16 g_fc_lo[(size_t)NP_OUT*KP_HH2];

// ---------------- helpers ----------------
__device__ __forceinline__ uint32_t smem_to_u32(const void* p) {
    uint32_t a;
    asm("{ .reg .u64 t; cvta.to.shared.u64 t, %1; cvt.u32.u64 %0, t; }" : "=r"(a) : "l"(p));
    return a;
}
#define SWZ(b) ((b) ^ (((b) >> 3) & 0x70))

__device__ __forceinline__ void cpasync16(uint32_t dst, const void* src) {
    asm volatile("cp.async.ca.shared.global [%0], [%1], 16;" :: "r"(dst), "l"(src));
}
__device__ __forceinline__ void ldsm_x4(uint32_t* r, uint32_t addr) {
    asm volatile("ldmatrix.sync.aligned.m8n8.x4.shared.b16 {%0,%1,%2,%3}, [%4];"
        : "=r"(r[0]), "=r"(r[1]), "=r"(r[2]), "=r"(r[3]) : "r"(addr));
}
__device__ __forceinline__ void mma_bf16(float* c, const uint32_t* a, const uint32_t* b) {
    asm volatile("mma.sync.aligned.m16n8k16.row.col.f32.bf16.bf16.f32 "
        "{%0,%1,%2,%3}, {%4,%5,%6,%7}, {%8,%9}, {%0,%1,%2,%3};"
        : "+f"(c[0]), "+f"(c[1]), "+f"(c[2]), "+f"(c[3])
        : "r"(a[0]), "r"(a[1]), "r"(a[2]), "r"(a[3]), "r"(b[0]), "r"(b[1]));
}

// permute original xg column n -> packed position
__device__ __forceinline__ int xg_perm(int gn) {
    int gate = (gn >= 2 * HID) ? 2 : ((gn >= HID) ? 1 : 0);
    int j = gn - gate * HID;
    return (j >> 6) * 192 + gate * 64 + (j & 63);
}

// ---------------- generic tensor-core GEMM (single-stage, occ2) ----------------
#define OFF_AHI 0
#define OFF_ALO 16384
#define OFF_BHI 32768
#define OFF_BLO 49152
#define STG_BYTES 65536
#define TG_SMEM (STG_BYTES + 3072 + 1024)

// mode 0: C = D + bias ; mode 2: attention partials ; mode 3: permuted xg store
__device__ __forceinline__ void tgemm_core(
    const __nv_bfloat16* __restrict__ Ahi, const __nv_bfloat16* __restrict__ Alo,
    const __nv_bfloat16* __restrict__ Bhi, const __nv_bfloat16* __restrict__ Blo,
    float* __restrict__ C, int ldc,
    const float* __restrict__ bias, const float* __restrict__ proj,
    float* __restrict__ partial, int nPart,
    int N, int Kpad, int mode)
{
    extern __shared__ char dsm[];
    uint32_t sraw = smem_to_u32(dsm);
    uint32_t sbase = (sraw + 1023) & ~1023u;
    char* sb = dsm + (sbase - sraw);

    const int tid  = threadIdx.x;
    const int lane = tid & 31;
    const int w    = tid >> 5;
    const int wm   = w >> 2;
    const int wn   = w & 3;
    const int g    = lane >> 2;
    const int tig  = lane & 3;
    const int m0   = blockIdx.y * 128;
    const int n0   = blockIdx.x * 128;

    float* bs  = (float*)(sb + STG_BYTES);
    float* ps  = (float*)(sb + STG_BYTES + 512);
    float* red = (float*)(sb + STG_BYTES + 1024);

    if (tid < 128) {
        int n = n0 + tid;
        bs[tid] = (n < N) ? bias[n] : 0.f;
        ps[tid] = (mode == 2 && n < N) ? proj[n] : 0.f;
    }

    float acc[4][4][4];
#pragma unroll
    for (int mt = 0; mt < 4; mt++)
#pragma unroll
        for (int nt = 0; nt < 4; nt++)
#pragma unroll
            for (int e = 0; e < 4; e++) acc[mt][nt][e] = 0.f;

    const int a_row  = wm * 64 + (lane & 7) + ((lane >> 3) & 1) * 8;
    const int a_bcol = ((lane >> 4) & 1) * 16;
    const int b_row  = wn * 32 + ((lane >> 4) & 1) * 8 + (lane & 7);
    const int b_bcol = ((lane >> 3) & 1) * 16;

    const int nc = Kpad >> 6;
    for (int c = 0; c < nc; c++) {
        const int k0 = c * 64;
#pragma unroll
        for (int i = 0; i < 4; i++) {
            int seg = i * 256 + tid;
            int row = seg >> 3, s = seg & 7;
            uint32_t sw = SWZ((uint32_t)(row * 128 + s * 16));
            size_t gA = (size_t)(m0 + row) * Kpad + k0 + s * 8;
            size_t gB = (size_t)(n0 + row) * Kpad + k0 + s * 8;
            cpasync16(sbase + OFF_AHI + sw, Ahi + gA);
            cpasync16(sbase + OFF_ALO + sw, Alo + gA);
            cpasync16(sbase + OFF_BHI + sw, Bhi + gB);
            cpasync16(sbase + OFF_BLO + sw, Blo + gB);
        }
        asm volatile("cp.async.commit_group;\n\tcp.async.wait_group 0;" ::: "memory");
        __syncthreads();

#pragma unroll
        for (int ks = 0; ks < 4; ks++) {
            uint32_t ah[4][4], al[4][4], bh[4][2], bl[4][2];
#pragma unroll
            for (int mt = 0; mt < 4; mt++) {
                uint32_t boff = (uint32_t)((a_row + mt * 16) * 128 + ks * 32 + a_bcol);
                ldsm_x4(ah[mt], sbase + OFF_AHI + SWZ(boff));
                ldsm_x4(al[mt], sbase + OFF_ALO + SWZ(boff));
            }
#pragma unroll
            for (int pr = 0; pr < 2; pr++) {
                uint32_t boff = (uint32_t)((b_row + pr * 16) * 128 + ks * 32 + b_bcol);
                uint32_t t[4];
                ldsm_x4(t, sbase + OFF_BHI + SWZ(boff));
                bh[pr*2][0] = t[0]; bh[pr*2][1] = t[1];
                bh[pr*2+1][0] = t[2]; bh[pr*2+1][1] = t[3];
                ldsm_x4(t, sbase + OFF_BLO + SWZ(boff));
                bl[pr*2][0] = t[0]; bl[pr*2][1] = t[1];
                bl[pr*2+1][0] = t[2]; bl[pr*2+1][1] = t[3];
            }
#pragma unroll
            for (int mt = 0; mt < 4; mt++)
#pragma unroll
                for (int nt = 0; nt < 4; nt++) {
                    mma_bf16(acc[mt][nt], ah[mt], bh[nt]);
                    mma_bf16(acc[mt][nt], ah[mt], bl[nt]);
                    mma_bf16(acc[mt][nt], al[mt], bh[nt]);
                }
        }
        __syncthreads();
    }

    if (mode == 2) {
#pragma unroll
        for (int mt = 0; mt < 4; mt++)
#pragma unroll
            for (int h = 0; h < 2; h++) {
                float s = 0.f;
#pragma unroll
                for (int nt = 0; nt < 4; nt++)
#pragma unroll
                    for (int e = 0; e < 2; e++) {
                        int ln = wn * 32 + nt * 8 + tig * 2 + e;
                        s += ps[ln] * tanhf(acc[mt][nt][h * 2 + e] + bs[ln]);
                    }
                s += __shfl_xor_sync(0xffffffffu, s, 1);
                s += __shfl_xor_sync(0xffffffffu, s, 2);
                if (tig == 0)
                    red[wn * 128 + wm * 64 + mt * 16 + h * 8 + g] = s;
            }
        __syncthreads();
        if (tid < 128) {
            float t = red[tid] + red[128 + tid] + red[256 + tid] + red[384 + tid];
            partial[(size_t)(m0 + tid) * nPart + blockIdx.x] = t;
        }
    } else {
#pragma unroll
        for (int mt = 0; mt < 4; mt++)
#pragma unroll
            for (int h = 0; h < 2; h++) {
                int gm = m0 + wm * 64 + mt * 16 + h * 8 + g;
#pragma unroll
                for (int nt = 0; nt < 4; nt++)
#pragma unroll
                    for (int e = 0; e < 2; e++) {
                        int ln = wn * 32 + nt * 8 + tig * 2 + e;
                        int gn = n0 + ln;
                        if (gn < N) {
                            float v = acc[mt][nt][h * 2 + e] + bs[ln];
                            int pos = (mode == 3) ? xg_perm(gn) : gn;
                            C[(size_t)gm * ldc + pos] = v;
                        }
                    }
            }
    }
}

// ---------------- GEMM wrappers ----------------
__global__ __launch_bounds__(256, 2) void k_tg_xg(const float* __restrict__ bihf,
                                                  const float* __restrict__ bihr) {
    int dir = blockIdx.z;
    tgemm_core(g_bag_hi, g_bag_lo,
               dir ? g_Wihr_hi : g_Wihf_hi, dir ? g_Wihr_lo : g_Wihf_lo,
               dir ? g_xg_r : g_xg_f, NP_G3, dir ? bihr : bihf, nullptr, nullptr, 0,
               G3, KP_IN, 3);
}
__global__ __launch_bounds__(256, 2) void k_tg_word(const float* __restrict__ b_word,
                                                    const float* __restrict__ proj_word) {
    tgemm_core(g_outb_hi, g_outb_lo, g_Ww_hi, g_Ww_lo,
               nullptr, 0, b_word, proj_word, g_partial, NPART,
               HH2, KP_HH2, 2);
}
__global__ __launch_bounds__(256, 2) void k_tg_usent(const float* __restrict__ b_sent,
                                                     const float* __restrict__ proj_sent) {
    tgemm_core(g_wv_hi, g_wv_lo, g_Ws_hi, g_Ws_lo,
               nullptr, 0, b_sent, proj_sent, g_partial2, NPART,
               HH2, KP_HH2, 2);
}
__global__ __launch_bounds__(256, 2) void k_tg_fc(const float* __restrict__ fcb) {
    tgemm_core(g_sv_hi, g_sv_lo, g_fc_hi, g_fc_lo,
               g_bagout, OUTD, fcb, nullptr, nullptr, 0,
               OUTD, KP_HH2, 0);
}

// ---------------- fused GRU step kernel ----------------
// grid (4 jtiles, 64 mtiles, 2 dirs), 128 threads (4 warps x 16 rows).
// GEMM: [64 batch rows] x [192 packed cols = 3 gates x 64 jl] x K=256,
// epilogue computes gates + h and writes all operand buffers.
#define GOF_AHI 0
#define GOF_ALO 8192
#define GOF_BHI 16384
#define GOF_BLO 40960
#define GRU_SMEM (65536 + 1024 + 1024)

__global__ __launch_bounds__(128, 3) void k_tg_gru(int i) {
    extern __shared__ char dsm[];
    uint32_t sraw = smem_to_u32(dsm);
    uint32_t sbase = (sraw + 1023) & ~1023u;
    char* sb = dsm + (sbase - sraw);

    const int tid  = threadIdx.x;
    const int lane = tid & 31;
    const int w    = tid >> 5;
    const int g    = lane >> 2;
    const int tig  = lane & 3;
    const int jt   = blockIdx.x;
    const int m0   = blockIdx.y * 64;
    const int dir  = blockIdx.z;

    const __nv_bfloat16* Ah = g_h_hi + (size_t)dir * BATCH * KP_HID;
    const __nv_bfloat16* Al = g_h_lo + (size_t)dir * BATCH * KP_HID;
    const __nv_bfloat16* Bh = g_Whhp_hi + (size_t)(dir * 4 + jt) * 192 * KP_HID;
    const __nv_bfloat16* Bl = g_Whhp_lo + (size_t)(dir * 4 + jt) * 192 * KP_HID;

    float* bs = (float*)(sb + 65536);
    if (tid < 128) {
        bs[tid] = g_bhhp[(dir * 4 + jt) * 192 + tid];
    }
    if (tid < 64) {
        bs[128 + tid] = g_bhhp[(dir * 4 + jt) * 192 + 128 + tid];
    }

    float acc[24][4];
#pragma unroll
    for (int nt = 0; nt < 24; nt++)
#pragma unroll
        for (int e = 0; e < 4; e++) acc[nt][e] = 0.f;

    const int a_row  = w * 16 + (lane & 7) + ((lane >> 3) & 1) * 8;
    const int a_bcol = ((lane >> 4) & 1) * 16;
    const int b_rsub = ((lane >> 4) & 1) * 8 + (lane & 7);
    const int b_bcol = ((lane >> 3) & 1) * 16;

    for (int c = 0; c < 4; c++) {
        const int k0 = c * 64;
        // A: 64 rows x 8 segs = 512 segs (hi+lo), 4+4 per thread
#pragma unroll
        for (int it = 0; it < 4; it++) {
            int seg = it * 128 + tid;
            int row = seg >> 3, s = seg & 7;
            uint32_t sw = SWZ((uint32_t)(row * 128 + s * 16));
            size_t gA = (size_t)(m0 + row) * KP_HID + k0 + s * 8;
            cpasync16(sbase + GOF_AHI + sw, Ah + gA);
            cpasync16(sbase + GOF_ALO + sw, Al + gA);
        }
        // B: 192 rows x 8 segs = 1536 segs (hi+lo), 12+12 per thread
#pragma unroll
        for (int it = 0; it < 12; it++) {
            int seg = it * 128 + tid;
            int row = seg >> 3, s = seg & 7;
            uint32_t sw = SWZ((uint32_t)(row * 128 + s * 16));
            size_t gB = (size_t)row * KP_HID + k0 + s * 8;
            cpasync16(sbase + GOF_BHI + sw, Bh + gB);
            cpasync16(sbase + GOF_BLO + sw, Bl + gB);
        }
        asm volatile("cp.async.commit_group;\n\tcp.async.wait_group 0;" ::: "memory");
        __syncthreads();

#pragma unroll
        for (int ks = 0; ks < 4; ks++) {
            uint32_t ah[4], al[4];
            uint32_t aoff = (uint32_t)(a_row * 128 + ks * 32 + a_bcol);
            ldsm_x4(ah, sbase + GOF_AHI + SWZ(aoff));
            ldsm_x4(al, sbase + GOF_ALO + SWZ(aoff));
#pragma unroll
            for (int pr = 0; pr < 12; pr++) {
                uint32_t boff = (uint32_t)((pr * 16 + b_rsub) * 128 + ks * 32 + b_bcol);
                uint32_t th[4], tl[4];
                ldsm_x4(th, sbase + GOF_BHI + SWZ(boff));
                ldsm_x4(tl, sbase + GOF_BLO + SWZ(boff));
                uint32_t b0h[2] = {th[0], th[1]}, b1h[2] = {th[2], th[3]};
                uint32_t b0l[2] = {tl[0], tl[1]}, b1l[2] = {tl[2], tl[3]};
                mma_bf16(acc[pr*2],   ah, b0h);
                mma_bf16(acc[pr*2],   ah, b0l);
                mma_bf16(acc[pr*2],   al, b0h);
                mma_bf16(acc[pr*2+1], ah, b1h);
                mma_bf16(acc[pr*2+1], ah, b1l);
                mma_bf16(acc[pr*2+1], al, b1h);
            }
        }
        __syncthreads();
    }

    // ---- gate epilogue ----
    const float* xgp = dir ? g_xg_r : g_xg_f;
    const int t  = dir ? (TLEN - 1 - i) : i;
    const int tp = dir ? (t + 1) : (t - 1);

#pragma unroll
    for (int h = 0; h < 2; h++) {
        int b = m0 + w * 16 + h * 8 + g;
        size_t xbase  = ((size_t)b * TLEN + t) * NP_G3 + jt * 192;
        size_t obase  = ((size_t)t * BATCH + b) * HH2 + dir * HID;
        size_t obb    = ((size_t)t * BATCH + b) * KP_HH2 + dir * HID;
        size_t hbase  = (size_t)dir * BATCH * KP_HID + (size_t)b * KP_HID;
        size_t pbase  = (i > 0) ? (((size_t)tp * BATCH + b) * HH2 + dir * HID) : 0;
#pragma unroll
        for (int jq = 0; jq < 8; jq++)
#pragma unroll
            for (int e = 0; e < 2; e++) {
                int jl = jq * 8 + tig * 2 + e;
                int j = jt * 64 + jl;
                if (j < HID) {
                    float rp = acc[jq][h * 2 + e]      + bs[jl];
                    float zp = acc[8 + jq][h * 2 + e]  + bs[64 + jl];
                    float np = acc[16 + jq][h * 2 + e] + bs[128 + jl];
                    float xr = xgp[xbase + jl];
                    float xz = xgp[xbase + 64 + jl];
                    float xn = xgp[xbase + 128 + jl];
                    float r = 1.f / (1.f + expf(-(xr + rp)));
                    float z = 1.f / (1.f + expf(-(xz + zp)));
                    float n = tanhf(xn + r * np);
                    float hp = (i > 0) ? g_out[pbase + j] : 0.f;
                    float hc = (1.f - z) * n + z * hp;
                    g_out[obase + j] = hc;
                    __nv_bfloat16 hh = __float2bfloat16(hc);
                    __nv_bfloat16 hl = __float2bfloat16(hc - __bfloat162float(hh));
                    g_h_hi[hbase + j] = hh;
                    g_h_lo[hbase + j] = hl;
                    g_outb_hi[obb + j] = hh;
                    g_outb_lo[obb + j] = hl;
                }
            }
    }
}

// ---------------- conversion / packing kernels ----------------
__device__ __forceinline__ void conv_body(const float* __restrict__ src,
                                          __nv_bfloat16* __restrict__ hi,
                                          __nv_bfloat16* __restrict__ lo,
                                          int M, int K, int Kpad, size_t total) {
    size_t idx = (size_t)blockIdx.x * blockDim.x + threadIdx.x;
    if (idx >= total) return;
    int m = (int)(idx / Kpad), k = (int)(idx - (size_t)m * Kpad);
    float x = (m < M && k < K) ? src[(size_t)m * K + k] : 0.f;
    __nv_bfloat16 h = __float2bfloat16(x);
    hi[idx] = h;
    lo[idx] = __float2bfloat16(x - __bfloat162float(h));
}
__device__ __forceinline__ void conv_bodyT(const float* __restrict__ src,
                                           __nv_bfloat16* __restrict__ hi,
                                           __nv_bfloat16* __restrict__ lo,
                                           int K, int N, int Kpad, size_t total) {
    size_t idx = (size_t)blockIdx.x * blockDim.x + threadIdx.x;
    if (idx >= total) return;
    int n = (int)(idx / Kpad), k = (int)(idx - (size_t)n * Kpad);
    float x = (n < N && k < K) ? src[(size_t)k * N + n] : 0.f;
    __nv_bfloat16 h = __float2bfloat16(x);
    hi[idx] = h;
    lo[idx] = __float2bfloat16(x - __bfloat162float(h));
}
__global__ void k_conv_bag(const float* __restrict__ s) {
    conv_body(s, g_bag_hi, g_bag_lo, MTOK, IND, KP_IN, (size_t)MTOK * KP_IN);
}
__global__ void k_conv_wihf(const float* __restrict__ s) {
    conv_body(s, g_Wihf_hi, g_Wihf_lo, G3, IND, KP_IN, (size_t)NP_G3 * KP_IN);
}
__global__ void k_conv_wihr(const float* __restrict__ s) {
    conv_body(s, g_Wihr_hi, g_Wihr_lo, G3, IND, KP_IN, (size_t)NP_G3 * KP_IN);
}
__global__ void k_conv_fcw(const float* __restrict__ s) {
    conv_body(s, g_fc_hi, g_fc_lo, OUTD, HH2, KP_HH2, (size_t)NP_OUT * KP_HH2);
}
__global__ void k_conv_ww(const float* __restrict__ s) {
    conv_bodyT(s, g_Ww_hi, g_Ww_lo, HH2, HH2, KP_HH2, (size_t)NP_HH2 * KP_HH2);
}
__global__ void k_conv_ws(const float* __restrict__ s) {
    conv_bodyT(s, g_Ws_hi, g_Ws_lo, HH2, HH2, KP_HH2, (size_t)NP_HH2 * KP_HH2);
}
// pack W_hh into (dir, jt, gate*64+jl, k) hi/lo + pack b_hh
__global__ void k_pack_whh(const float* __restrict__ Wf, const float* __restrict__ Wr,
                           const float* __restrict__ bf, const float* __restrict__ br) {
    size_t idx = (size_t)blockIdx.x * blockDim.x + threadIdx.x;
    size_t total = (size_t)2 * 4 * 192 * KP_HID;
    if (idx >= total) return;
    int k = (int)(idx & (KP_HID - 1));
    int rowp = (int)((idx >> 8) % 192);
    int jt = (int)((idx >> 8) / 192 % 4);
    int dir = (int)(idx / ((size_t)4 * 192 * KP_HID));
    int gate = rowp / 64, jl = rowp % 64;
    int j = jt * 64 + jl;
    const float* W = dir ? Wr : Wf;
    float x = (j < HID && k < HID) ? W[(size_t)(gate * HID + j) * HID + k] : 0.f;
    __nv_bfloat16 h = __float2bfloat16(x);
    g_Whhp_hi[idx] = h;
    g_Whhp_lo[idx] = __float2bfloat16(x - __bfloat162float(h));
    if (k == 0) {
        const float* bb = dir ? br : bf;
        g_bhhp[(dir * 4 + jt) * 192 + rowp] = (j < HID) ? bb[gate * HID + j] : 0.f;
    }
}
__global__ void k_zero_h() {
    int idx = blockIdx.x * blockDim.x + threadIdx.x;
    if (idx >= 2 * BATCH * KP_HID) return;
    __nv_bfloat16 z = __float2bfloat16(0.f);
    g_h_hi[idx] = z;
    g_h_lo[idx] = z;
}
__global__ void k_zero_outb_pad() {
    size_t idx = (size_t)blockIdx.x * blockDim.x + threadIdx.x;
    size_t total = (size_t)MTOK * (KP_HH2 - HH2);
    if (idx >= total) return;
    int row = (int)(idx / (KP_HH2 - HH2));
    int col = HH2 + (int)(idx % (KP_HH2 - HH2));
    size_t o = (size_t)row * KP_HH2 + col;
    __nv_bfloat16 z = __float2bfloat16(0.f);
    g_outb_hi[o] = z;
    g_outb_lo[o] = z;
}

// ---------------- elementwise kernels ----------------
__global__ void k_reduce_word() {
    int m = blockIdx.x * blockDim.x + threadIdx.x;
    if (m >= MTOK) return;
    float s = 0.f;
#pragma unroll
    for (int p = 0; p < NPART; p++) s += g_partial[(size_t)m * NPART + p];
    int t = m / BATCH, b = m - t * BATCH;
    g_scores[(size_t)b * TLEN + t] = s;
}
__global__ void k_softmax_word() {
    int warp = threadIdx.x >> 5, lane = threadIdx.x & 31;
    int b = blockIdx.x * (blockDim.x >> 5) + warp;
    if (b >= BATCH) return;
    float v0 = g_scores[b * TLEN + lane];
    float v1 = g_scores[b * TLEN + lane + 32];
    float m = fmaxf(v0, v1);
#pragma unroll
    for (int o = 16; o > 0; o >>= 1) m = fmaxf(m, __shfl_xor_sync(0xffffffffu, m, o));
    float e0 = expf(v0 - m), e1 = expf(v1 - m);
    float s = e0 + e1;
#pragma unroll
    for (int o = 16; o > 0; o >>= 1) s += __shfl_xor_sync(0xffffffffu, s, o);
    float inv = 1.f / s;
    g_scores[b * TLEN + lane]      = e0 * inv;
    g_scores[b * TLEN + lane + 32] = e1 * inv;
}
__global__ void k_wordvec() {
    size_t idx = (size_t)blockIdx.x * blockDim.x + threadIdx.x;
    if (idx >= (size_t)BATCH * KP_HH2) return;
    int b = (int)(idx / KP_HH2), h = (int)(idx - (size_t)b * KP_HH2);
    float s = 0.f;
    if (h < HH2) {
#pragma unroll 4
        for (int t = 0; t < TLEN; t++)
            s += g_scores[b * TLEN + t] * g_out[((size_t)t * BATCH + b) * HH2 + h];
        g_wordvec[(size_t)b * HH2 + h] = s;
    }
    __nv_bfloat16 sh = __float2bfloat16(s);
    g_wv_hi[idx] = sh;
    g_wv_lo[idx] = __float2bfloat16(s - __bfloat162float(sh));
}
__global__ void k_reduce_sent() {
    int b = blockIdx.x * blockDim.x + threadIdx.x;
    if (b >= BATCH) return;
    float s = 0.f;
#pragma unroll
    for (int p = 0; p < NPART; p++) s += g_partial2[(size_t)b * NPART + p];
    g_scores2[b] = s;
}
__global__ void k_softmax_sent() {
    int nb = blockIdx.x * blockDim.x + threadIdx.x;
    if (nb >= NBAGS) return;
    float m = -1e30f;
#pragma unroll
    for (int s = 0; s < MSENT; s++) m = fmaxf(m, g_scores2[nb * MSENT + s]);
    float sum = 0.f;
    float e[MSENT];
#pragma unroll
    for (int s = 0; s < MSENT; s++) { e[s] = expf(g_scores2[nb * MSENT + s] - m); sum += e[s]; }
    float inv = 1.f / sum;
#pragma unroll
    for (int s = 0; s < MSENT; s++) g_scores2[nb * MSENT + s] = e[s] * inv;
}
__global__ void k_sentvec() {
    size_t idx = (size_t)blockIdx.x * blockDim.x + threadIdx.x;
    if (idx >= (size_t)NBAGS * KP_HH2) return;
    int nb = (int)(idx / KP_HH2), h = (int)(idx - (size_t)nb * KP_HH2);
    float s = 0.f;
    if (h < HH2) {
#pragma unroll
        for (int ss = 0; ss < MSENT; ss++)
            s += g_scores2[nb * MSENT + ss] * g_wordvec[(size_t)(nb * MSENT + ss) * HH2 + h];
    }
    __nv_bfloat16 sh = __float2bfloat16(s);
    g_sv_hi[idx] = sh;
    g_sv_lo[idx] = __float2bfloat16(s - __bfloat162float(sh));
}
__global__ void k_zero(float* __restrict__ out, int n) {
    int idx = blockIdx.x * blockDim.x + threadIdx.x;
    if (idx < n) out[idx] = 0.f;
}
__global__ void k_scatter(const int* __restrict__ pairs, float* __restrict__ out) {
    int idx = blockIdx.x * blockDim.x + threadIdx.x;
    if (idx >= NBAGS * OUTD) return;
    int b = idx / OUTD, o = idx - b * OUTD;
    int p0 = pairs[b * 3 + 0], p1 = pairs[b * 3 + 1], p2 = pairs[b * 3 + 2];
    out[((size_t)(p0 * NENT + p1) * NENT + p2) * OUTD + o] = g_bagout[idx];
}

// ---------------- launch ----------------
extern "C" void kernel_launch(void* const* d_in, const int* in_sizes, int n_in,
                              void* d_out, int out_size) {
    const float* bag       = (const float*)d_in[0];
    const float* W_ih_f    = (const float*)d_in[1];
    const float* W_hh_f    = (const float*)d_in[2];
    const float* b_ih_f    = (const float*)d_in[3];
    const float* b_hh_f    = (const float*)d_in[4];
    const float* W_ih_r    = (const float*)d_in[5];
    const float* W_hh_r    = (const float*)d_in[6];
    const float* b_ih_r    = (const float*)d_in[7];
    const float* b_hh_r    = (const float*)d_in[8];
    const float* W_word    = (const float*)d_in[9];
    const float* b_word    = (const float*)d_in[10];
    const float* proj_word = (const float*)d_in[11];
    const float* W_sent    = (const float*)d_in[12];
    const float* b_sent    = (const float*)d_in[13];
    const float* proj_sent = (const float*)d_in[14];
    const float* fc_W      = (const float*)d_in[15];
    const float* fc_b      = (const float*)d_in[16];
    const int*   pairs     = (const int*)d_in[17];
    float* out = (float*)d_out;

    cudaFuncSetAttribute(k_tg_xg,    cudaFuncAttributeMaxDynamicSharedMemorySize, TG_SMEM);
    cudaFuncSetAttribute(k_tg_word,  cudaFuncAttributeMaxDynamicSharedMemorySize, TG_SMEM);
    cudaFuncSetAttribute(k_tg_usent, cudaFuncAttributeMaxDynamicSharedMemorySize, TG_SMEM);
    cudaFuncSetAttribute(k_tg_fc,    cudaFuncAttributeMaxDynamicSharedMemorySize, TG_SMEM);
    cudaFuncSetAttribute(k_tg_gru,   cudaFuncAttributeMaxDynamicSharedMemorySize, GRU_SMEM);

    // conversions + packing
    k_conv_bag <<<(int)(((size_t)MTOK * KP_IN + 255) / 256), 256>>>(bag);
    k_conv_wihf<<<(NP_G3 * KP_IN + 255) / 256, 256>>>(W_ih_f);
    k_conv_wihr<<<(NP_G3 * KP_IN + 255) / 256, 256>>>(W_ih_r);
    k_pack_whh <<<(int)(((size_t)2 * 4 * 192 * KP_HID + 255) / 256), 256>>>(W_hh_f, W_hh_r, b_hh_f, b_hh_r);
    k_conv_fcw <<<(NP_OUT * KP_HH2 + 255) / 256, 256>>>(fc_W);
    k_conv_ww  <<<(NP_HH2 * KP_HH2 + 255) / 256, 256>>>(W_word);
    k_conv_ws  <<<(NP_HH2 * KP_HH2 + 255) / 256, 256>>>(W_sent);
    k_zero_h   <<<(2 * BATCH * KP_HID + 255) / 256, 256>>>();
    k_zero_outb_pad<<<(int)(((size_t)MTOK * (KP_HH2 - HH2) + 255) / 256), 256>>>();

    // input projections (permuted store)
    k_tg_xg<<<dim3(NP_G3 / 128, MTOK / 128, 2), 256, TG_SMEM>>>(b_ih_f, b_ih_r);

    // fused GRU recurrence: one kernel per step
    for (int i = 0; i < TLEN; i++)
        k_tg_gru<<<dim3(4, BATCH / 64, 2), 128, GRU_SMEM>>>(i);

    // word attention
    k_tg_word<<<dim3(NP_HH2 / 128, MTOK / 128), 256, TG_SMEM>>>(b_word, proj_word);
    k_reduce_word<<<(MTOK + 255) / 256, 256>>>();
    k_softmax_word<<<BATCH / 8, 256>>>();
    k_wordvec<<<(int)(((size_t)BATCH * KP_HH2 + 255) / 256), 256>>>();

    // sentence attention
    k_tg_usent<<<dim3(NP_HH2 / 128, BATCH / 128), 256, TG_SMEM>>>(b_sent, proj_sent);
    k_reduce_sent<<<(BATCH + 255) / 256, 256>>>();
    k_softmax_sent<<<(NBAGS + 255) / 256, 256>>>();
    k_sentvec<<<(int)(((size_t)NBAGS * KP_HH2 + 255) / 256), 256>>>();

    // classifier + scatter
    k_tg_fc<<<dim3(1, NBAGS / 128), 256, TG_SMEM>>>(fc_b);
    k_zero<<<(out_size + 255) / 256, 256>>>(out, out_size);
    k_scatter<<<(NBAGS * OUTD + 255) / 256, 256>>>(pairs, out);
}